// round 1
// baseline (speedup 1.0000x reference)
#include <cuda_runtime.h>
#include <math.h>
#include <stddef.h>

// ---------------- problem constants ----------------
#define BWIN   4096          // B_ = B * nW = 64*64 windows
#define NTOK   49
#define DIMC   256
#define NH     8
#define HD     32
#define TDIM   768
#define MROWS  (BWIN * NTOK) // 200704

// ---------------- scratch (device globals; no allocation allowed) ----------------
__device__ float g_qkv[(size_t)MROWS * TDIM];      // 616 MB
__device__ float g_attnout[(size_t)MROWS * DIMC];  // 205 MB
__device__ float g_table[169 * NH];
__device__ float g_bias768[TDIM];

// ---------------- tiny setup kernels ----------------
__global__ void fill_bias_kernel(const float* __restrict__ q_bias,
                                 const float* __restrict__ v_bias) {
    int t = threadIdx.x;
    if (t < 256)       g_bias768[t] = q_bias[t];
    else if (t < 512)  g_bias768[t] = 0.f;
    else               g_bias768[t] = v_bias[t - 512];
}

// CPB MLP: table[r][h] = (relu(coords[r] @ w1^T + b1) @ w2^T)[h], r in [0,169)
__global__ void cpb_table_kernel(const float* __restrict__ coords,   // (169,2)
                                 const float* __restrict__ w1,       // (512,2)
                                 const float* __restrict__ b1,       // (512,)
                                 const float* __restrict__ w2) {     // (8,512)
    __shared__ float hid[512];
    __shared__ float part[64];
    int r = blockIdx.x;
    int tid = threadIdx.x;
    float c0 = coords[r * 2 + 0];
    float c1 = coords[r * 2 + 1];
    for (int j = tid; j < 512; j += 64) {
        float v = c0 * w1[j * 2 + 0] + c1 * w1[j * 2 + 1] + b1[j];
        hid[j] = v > 0.f ? v : 0.f;
    }
    __syncthreads();
    int head = tid & 7;
    int chunk = tid >> 3;      // 0..7, each covers 64 hidden units
    float p = 0.f;
    const float* wrow = w2 + head * 512 + chunk * 64;
    const float* hrow = hid + chunk * 64;
#pragma unroll 8
    for (int j = 0; j < 64; ++j) p += hrow[j] * wrow[j];
    part[tid] = p;
    __syncthreads();
    if (tid < 8) {
        float s = 0.f;
#pragma unroll
        for (int c = 0; c < 8; ++c) s += part[c * 8 + tid];
        g_table[r * 8 + tid] = s;
    }
}

// ---------------- SGEMM: C[M,N] = A[M,K] @ W[N,K]^T + bias[N] ----------------
// Tiles: 128x128x16, 256 threads, 8x8 per thread. M%128==0, N%128==0, K%16==0.
__global__ __launch_bounds__(256)
void sgemm_bias(const float* __restrict__ A, const float* __restrict__ W,
                const float* __restrict__ bias, float* __restrict__ C,
                int M, int N, int K) {
    __shared__ float As[16][132];
    __shared__ float Bs[16][132];

    int tid = threadIdx.x;
    size_t rowBase = (size_t)blockIdx.y * 128;
    int colBase = blockIdx.x * 128;

    int ty = tid >> 4;       // 0..15
    int tx = tid & 15;       // 0..15

    float acc[8][8];
#pragma unroll
    for (int i = 0; i < 8; ++i)
#pragma unroll
        for (int j = 0; j < 8; ++j) acc[i][j] = 0.f;

    for (int k0 = 0; k0 < K; k0 += 16) {
#pragma unroll
        for (int ld = 0; ld < 2; ++ld) {
            int f4 = tid + ld * 256;       // 0..511
            int r  = f4 >> 2;              // 0..127
            int kq = (f4 & 3) << 2;        // 0,4,8,12
            float4 a = *(const float4*)(A + (rowBase + r) * (size_t)K + k0 + kq);
            As[kq + 0][r] = a.x; As[kq + 1][r] = a.y;
            As[kq + 2][r] = a.z; As[kq + 3][r] = a.w;
            float4 w = *(const float4*)(W + (size_t)(colBase + r) * K + k0 + kq);
            Bs[kq + 0][r] = w.x; Bs[kq + 1][r] = w.y;
            Bs[kq + 2][r] = w.z; Bs[kq + 3][r] = w.w;
        }
        __syncthreads();
#pragma unroll
        for (int k = 0; k < 16; ++k) {
            float4 a0 = *(const float4*)&As[k][ty * 8];
            float4 a1 = *(const float4*)&As[k][ty * 8 + 4];
            float4 b0 = *(const float4*)&Bs[k][tx * 8];
            float4 b1 = *(const float4*)&Bs[k][tx * 8 + 4];
            float av[8] = {a0.x, a0.y, a0.z, a0.w, a1.x, a1.y, a1.z, a1.w};
            float bv[8] = {b0.x, b0.y, b0.z, b0.w, b1.x, b1.y, b1.z, b1.w};
#pragma unroll
            for (int i = 0; i < 8; ++i)
#pragma unroll
                for (int j = 0; j < 8; ++j)
                    acc[i][j] = fmaf(av[i], bv[j], acc[i][j]);
        }
        __syncthreads();
    }

    float4 bi0 = *(const float4*)(bias + colBase + tx * 8);
    float4 bi1 = *(const float4*)(bias + colBase + tx * 8 + 4);
#pragma unroll
    for (int i = 0; i < 8; ++i) {
        size_t m = rowBase + ty * 8 + i;
        float* crow = C + m * (size_t)N + colBase + tx * 8;
        float4 o0, o1;
        o0.x = acc[i][0] + bi0.x; o0.y = acc[i][1] + bi0.y;
        o0.z = acc[i][2] + bi0.z; o0.w = acc[i][3] + bi0.w;
        o1.x = acc[i][4] + bi1.x; o1.y = acc[i][5] + bi1.y;
        o1.z = acc[i][6] + bi1.z; o1.w = acc[i][7] + bi1.w;
        *(float4*)(crow)     = o0;
        *(float4*)(crow + 4) = o1;
    }
}

// ---------------- attention kernel: one block per (window, head) ----------------
__global__ __launch_bounds__(256)
void attn_kernel(const float* __restrict__ logit_scale,   // (8,)
                 const int*   __restrict__ rpi,           // (49,49)
                 const float* __restrict__ mask) {        // (64,49,49)
    __shared__ float sq[49][33];
    __shared__ float sk[52][33];
    __shared__ float sv[49][33];
    __shared__ float sattn[52][52];

    int blk = blockIdx.x;          // 0..32767
    int b = blk >> 3;              // window index 0..4095
    int h = blk & 7;
    int tid = threadIdx.x;
    int wid = tid >> 5, lane = tid & 31;

    // load q,k,v tiles for this (b,h)
    for (int idx = tid; idx < NTOK * HD; idx += 256) {
        int n = idx >> 5, d = idx & 31;
        size_t base = ((size_t)b * NTOK + n) * TDIM + h * HD + d;
        sq[n][d] = g_qkv[base];
        sk[n][d] = g_qkv[base + 256];
        sv[n][d] = g_qkv[base + 512];
    }
    if (tid < 96) sk[49 + (tid >> 5)][tid & 31] = 0.f;       // pad k rows
    if (tid < 3 * 52) sattn[49 + tid / 52][tid % 52] = 0.f;  // pad attn rows
    __syncthreads();

    float sc = expf(fminf(logit_scale[h], 4.60517019f));     // clamp at ln(100)

    // cosine-normalize rows (fold logit scale into q)
    for (int r = wid; r < NTOK; r += 8) {
        float qv = sq[r][lane];
        float s = qv * qv;
#pragma unroll
        for (int o = 16; o; o >>= 1) s += __shfl_xor_sync(0xffffffffu, s, o);
        sq[r][lane] = qv * rsqrtf(s + 1e-6f) * sc;
        float kv = sk[r][lane];
        float s2 = kv * kv;
#pragma unroll
        for (int o = 16; o; o >>= 1) s2 += __shfl_xor_sync(0xffffffffu, s2, o);
        sk[r][lane] = kv * rsqrtf(s2 + 1e-6f);
    }
    __syncthreads();

    // attn logits: 49 rows x 13 strips of 4 cols
    int wmask = (b & 63) * (NTOK * NTOK);
    for (int s = tid; s < NTOK * 13; s += 256) {
        int i = s / 13;
        int j0 = (s % 13) * 4;
        float a0 = 0.f, a1 = 0.f, a2 = 0.f, a3 = 0.f;
#pragma unroll
        for (int d = 0; d < HD; ++d) {
            float qv = sq[i][d];
            a0 = fmaf(qv, sk[j0 + 0][d], a0);
            a1 = fmaf(qv, sk[j0 + 1][d], a1);
            a2 = fmaf(qv, sk[j0 + 2][d], a2);
            a3 = fmaf(qv, sk[j0 + 3][d], a3);
        }
        float av[4] = {a0, a1, a2, a3};
#pragma unroll
        for (int u = 0; u < 4; ++u) {
            int j = j0 + u;
            if (j < NTOK) {
                float t = g_table[rpi[i * NTOK + j] * NH + h];
                float rpb = 16.f / (1.f + expf(-t));
                sattn[i][j] = av[u] + rpb + mask[wmask + i * NTOK + j];
            }
        }
    }
    __syncthreads();

    // row softmax: warp per row
    for (int r = wid; r < NTOK; r += 8) {
        float v0 = sattn[r][lane];
        float v1 = (lane + 32 < NTOK) ? sattn[r][lane + 32] : -1e30f;
        float mx = fmaxf(v0, v1);
#pragma unroll
        for (int o = 16; o; o >>= 1) mx = fmaxf(mx, __shfl_xor_sync(0xffffffffu, mx, o));
        float e0 = expf(v0 - mx);
        float e1 = (lane + 32 < NTOK) ? expf(v1 - mx) : 0.f;
        float sm = e0 + e1;
#pragma unroll
        for (int o = 16; o; o >>= 1) sm += __shfl_xor_sync(0xffffffffu, sm, o);
        float inv = 1.f / sm;
        sattn[r][lane] = e0 * inv;
        if (lane + 32 < NTOK) sattn[r][lane + 32] = e1 * inv;
    }
    __syncthreads();

    // out = attn @ v : 13 i-strips of 4 x 32 d
    for (int s = tid; s < 13 * 32; s += 256) {
        int istrip = s >> 5;
        int d = s & 31;
        int i0 = istrip * 4;
        float o0 = 0.f, o1 = 0.f, o2 = 0.f, o3 = 0.f;
        for (int j = 0; j < NTOK; ++j) {
            float vv = sv[j][d];
            o0 = fmaf(sattn[i0 + 0][j], vv, o0);
            o1 = fmaf(sattn[i0 + 1][j], vv, o1);
            o2 = fmaf(sattn[i0 + 2][j], vv, o2);
            o3 = fmaf(sattn[i0 + 3][j], vv, o3);
        }
        float ov[4] = {o0, o1, o2, o3};
#pragma unroll
        for (int u = 0; u < 4; ++u) {
            int i = i0 + u;
            if (i < NTOK)
                g_attnout[((size_t)b * NTOK + i) * DIMC + h * HD + d] = ov[u];
        }
    }
}

// ---------------- launch ----------------
extern "C" void kernel_launch(void* const* d_in, const int* in_sizes, int n_in,
                              void* d_out, int out_size) {
    const float* x           = (const float*)d_in[0];
    const float* qkv_w       = (const float*)d_in[1];
    const float* q_bias      = (const float*)d_in[2];
    const float* v_bias      = (const float*)d_in[3];
    const float* logit_scale = (const float*)d_in[4];
    const float* cpb_w1      = (const float*)d_in[5];
    const float* cpb_b1      = (const float*)d_in[6];
    const float* cpb_w2      = (const float*)d_in[7];
    const float* coords      = (const float*)d_in[8];
    const int*   rpi         = (const int*)  d_in[9];
    const float* mask        = (const float*)d_in[10];
    const float* proj_w      = (const float*)d_in[11];
    const float* proj_b      = (const float*)d_in[12];
    float* out = (float*)d_out;

    float *qkv_ptr = nullptr, *ao_ptr = nullptr, *b768_ptr = nullptr;
    cudaGetSymbolAddress((void**)&qkv_ptr, g_qkv);
    cudaGetSymbolAddress((void**)&ao_ptr, g_attnout);
    cudaGetSymbolAddress((void**)&b768_ptr, g_bias768);

    fill_bias_kernel<<<1, 768>>>(q_bias, v_bias);
    cpb_table_kernel<<<169, 64>>>(coords, cpb_w1, cpb_b1, cpb_w2);

    // qkv = x @ qkv_w^T + [q_bias, 0, v_bias]
    sgemm_bias<<<dim3(TDIM / 128, MROWS / 128), 256>>>(
        x, qkv_w, b768_ptr, qkv_ptr, MROWS, TDIM, DIMC);

    // per-(window, head) cosine attention
    attn_kernel<<<BWIN * NH, 256>>>(logit_scale, rpi, mask);

    // out = attn_out @ proj_w^T + proj_b
    sgemm_bias<<<dim3(DIMC / 128, MROWS / 128), 256>>>(
        ao_ptr, proj_w, proj_b, out, MROWS, DIMC, DIMC);
}

// round 2
// speedup vs baseline: 1.5589x; 1.5589x over previous
#include <cuda_runtime.h>
#include <math.h>
#include <stddef.h>
#include <stdint.h>

// ---------------- problem constants ----------------
#define BWIN   4096          // B_ = B * nW = 64*64 windows
#define NTOK   49
#define DIMC   256
#define NH     8
#define HD     32
#define TDIM   768
#define MROWS  (BWIN * NTOK) // 200704

// ---------------- scratch (device globals; no allocation allowed) ----------------
__device__ float g_qkv[(size_t)MROWS * TDIM];      // 616 MB
__device__ float g_attnout[(size_t)MROWS * DIMC];  // 205 MB
__device__ float g_table[169 * NH];
__device__ float g_bias768[TDIM];

// ---------------- tiny setup kernels ----------------
__global__ void fill_bias_kernel(const float* __restrict__ q_bias,
                                 const float* __restrict__ v_bias) {
    int t = threadIdx.x;
    if (t < 256)       g_bias768[t] = q_bias[t];
    else if (t < 512)  g_bias768[t] = 0.f;
    else               g_bias768[t] = v_bias[t - 512];
}

// CPB MLP: table[r][h] = (relu(coords[r] @ w1^T + b1) @ w2^T)[h], r in [0,169)
__global__ void cpb_table_kernel(const float* __restrict__ coords,   // (169,2)
                                 const float* __restrict__ w1,       // (512,2)
                                 const float* __restrict__ b1,       // (512,)
                                 const float* __restrict__ w2) {     // (8,512)
    __shared__ float hid[512];
    __shared__ float part[64];
    int r = blockIdx.x;
    int tid = threadIdx.x;
    float c0 = coords[r * 2 + 0];
    float c1 = coords[r * 2 + 1];
    for (int j = tid; j < 512; j += 64) {
        float v = c0 * w1[j * 2 + 0] + c1 * w1[j * 2 + 1] + b1[j];
        hid[j] = v > 0.f ? v : 0.f;
    }
    __syncthreads();
    int head = tid & 7;
    int chunk = tid >> 3;
    float p = 0.f;
    const float* wrow = w2 + head * 512 + chunk * 64;
    const float* hrow = hid + chunk * 64;
#pragma unroll 8
    for (int j = 0; j < 64; ++j) p += hrow[j] * wrow[j];
    part[tid] = p;
    __syncthreads();
    if (tid < 8) {
        float s = 0.f;
#pragma unroll
        for (int c = 0; c < 8; ++c) s += part[c * 8 + tid];
        g_table[r * 8 + tid] = s;
    }
}

// ---------------- TF32 tensor-core GEMM ----------------
// C[M,N] = A[M,K] @ W[N,K]^T + bias[N]
// Block: 128x128 tile, 256 threads (8 warps, 2 in M x 4 in N), warp tile 64x32.
// K chunked by 32, single smem buffer + register prefetch pipeline.
// M%128==0, N%128==0, K%32==0.

__device__ __forceinline__ uint32_t f2tf32(float x) {
    uint32_t r;
    asm("cvt.rna.tf32.f32 %0, %1;" : "=r"(r) : "f"(x));
    return r;
}

__device__ __forceinline__ void mma_tf32(float c[4], uint32_t a0, uint32_t a1,
                                         uint32_t a2, uint32_t a3,
                                         uint32_t b0, uint32_t b1) {
    asm volatile(
        "mma.sync.aligned.m16n8k8.row.col.f32.tf32.tf32.f32 "
        "{%0,%1,%2,%3}, {%4,%5,%6,%7}, {%8,%9}, {%0,%1,%2,%3};"
        : "+f"(c[0]), "+f"(c[1]), "+f"(c[2]), "+f"(c[3])
        : "r"(a0), "r"(a1), "r"(a2), "r"(a3), "r"(b0), "r"(b1));
}

#define LDPAD 36   // 32 k-words padded to 36 (conflict-free fragment reads)

__global__ __launch_bounds__(256)
void gemm_tf32(const float* __restrict__ A, const float* __restrict__ W,
               const float* __restrict__ bias, float* __restrict__ C,
               int M, int N, int K) {
    __shared__ uint32_t As[128 * LDPAD];
    __shared__ uint32_t Ws[128 * LDPAD];

    int tid = threadIdx.x;
    int lane = tid & 31, wid = tid >> 5;
    int g = lane >> 2, tig = lane & 3;
    int warpM = wid & 1;     // 2 warps in M (64 rows each)
    int warpN = wid >> 1;    // 4 warps in N (32 cols each)
    size_t rowBlk = (size_t)blockIdx.y * 128;
    int colBlk = blockIdx.x * 128;

    float c[4][4][4];
#pragma unroll
    for (int mt = 0; mt < 4; ++mt)
#pragma unroll
        for (int nt = 0; nt < 4; ++nt)
#pragma unroll
            for (int u = 0; u < 4; ++u) c[mt][nt][u] = 0.f;

    const int NCH = K >> 5;   // chunks of 32
    float4 pa[4], pw[4];
    // each thread's fixed (row, col-quad) within the 128x32 stage
    int f_r[4], f_c[4];
#pragma unroll
    for (int ld = 0; ld < 4; ++ld) {
        int f = tid + ld * 256;     // 0..1023 float4 slots
        f_r[ld] = f >> 3;           // 0..127
        f_c[ld] = (f & 7) << 2;     // 0,4,...,28
    }

    // prologue: load chunk 0
#pragma unroll
    for (int ld = 0; ld < 4; ++ld) {
        pa[ld] = *(const float4*)(A + (rowBlk + f_r[ld]) * (size_t)K + f_c[ld]);
        pw[ld] = *(const float4*)(W + (size_t)(colBlk + f_r[ld]) * K + f_c[ld]);
    }
#pragma unroll
    for (int ld = 0; ld < 4; ++ld) {
        uint32_t* pA = &As[f_r[ld] * LDPAD + f_c[ld]];
        pA[0] = f2tf32(pa[ld].x); pA[1] = f2tf32(pa[ld].y);
        pA[2] = f2tf32(pa[ld].z); pA[3] = f2tf32(pa[ld].w);
        uint32_t* pW = &Ws[f_r[ld] * LDPAD + f_c[ld]];
        pW[0] = f2tf32(pw[ld].x); pW[1] = f2tf32(pw[ld].y);
        pW[2] = f2tf32(pw[ld].z); pW[3] = f2tf32(pw[ld].w);
    }
    __syncthreads();

    for (int ch = 0; ch < NCH; ++ch) {
        if (ch + 1 < NCH) {
            int k0 = (ch + 1) << 5;
#pragma unroll
            for (int ld = 0; ld < 4; ++ld) {
                pa[ld] = *(const float4*)(A + (rowBlk + f_r[ld]) * (size_t)K + k0 + f_c[ld]);
                pw[ld] = *(const float4*)(W + (size_t)(colBlk + f_r[ld]) * K + k0 + f_c[ld]);
            }
        }

#pragma unroll
        for (int kk = 0; kk < 32; kk += 8) {
            uint32_t af[4][4], bf[4][2];
#pragma unroll
            for (int mt = 0; mt < 4; ++mt) {
                int r0 = warpM * 64 + mt * 16;
                af[mt][0] = As[(r0 + g) * LDPAD + kk + tig];
                af[mt][1] = As[(r0 + g + 8) * LDPAD + kk + tig];
                af[mt][2] = As[(r0 + g) * LDPAD + kk + tig + 4];
                af[mt][3] = As[(r0 + g + 8) * LDPAD + kk + tig + 4];
            }
#pragma unroll
            for (int nt = 0; nt < 4; ++nt) {
                int n0 = warpN * 32 + nt * 8;
                bf[nt][0] = Ws[(n0 + g) * LDPAD + kk + tig];
                bf[nt][1] = Ws[(n0 + g) * LDPAD + kk + tig + 4];
            }
#pragma unroll
            for (int mt = 0; mt < 4; ++mt)
#pragma unroll
                for (int nt = 0; nt < 4; ++nt)
                    mma_tf32(c[mt][nt], af[mt][0], af[mt][1], af[mt][2], af[mt][3],
                             bf[nt][0], bf[nt][1]);
        }

        if (ch + 1 < NCH) {
            __syncthreads();
#pragma unroll
            for (int ld = 0; ld < 4; ++ld) {
                uint32_t* pA = &As[f_r[ld] * LDPAD + f_c[ld]];
                pA[0] = f2tf32(pa[ld].x); pA[1] = f2tf32(pa[ld].y);
                pA[2] = f2tf32(pa[ld].z); pA[3] = f2tf32(pa[ld].w);
                uint32_t* pW = &Ws[f_r[ld] * LDPAD + f_c[ld]];
                pW[0] = f2tf32(pw[ld].x); pW[1] = f2tf32(pw[ld].y);
                pW[2] = f2tf32(pw[ld].z); pW[3] = f2tf32(pw[ld].w);
            }
            __syncthreads();
        }
    }

    // epilogue: c[mt][nt] -> rows (g, g+8), cols (2*tig, 2*tig+1)
#pragma unroll
    for (int nt = 0; nt < 4; ++nt) {
        int col = colBlk + warpN * 32 + nt * 8 + 2 * tig;
        float2 bv = *(const float2*)(bias + col);
#pragma unroll
        for (int mt = 0; mt < 4; ++mt) {
            size_t row0 = rowBlk + warpM * 64 + mt * 16;
            float2 o0, o1;
            o0.x = c[mt][nt][0] + bv.x; o0.y = c[mt][nt][1] + bv.y;
            o1.x = c[mt][nt][2] + bv.x; o1.y = c[mt][nt][3] + bv.y;
            *(float2*)(C + (row0 + g) * (size_t)N + col)     = o0;
            *(float2*)(C + (row0 + g + 8) * (size_t)N + col) = o1;
        }
    }
}

// ---------------- attention kernel: one block per (window, head) ----------------
__global__ __launch_bounds__(256)
void attn_kernel(const float* __restrict__ logit_scale,   // (8,)
                 const int*   __restrict__ rpi,           // (49,49)
                 const float* __restrict__ mask) {        // (64,49,49)
    __shared__ float sq[49][33];
    __shared__ float sk[52][33];
    __shared__ float sv[49][33];
    __shared__ float sattn[52][52];

    int blk = blockIdx.x;          // 0..32767
    int b = blk >> 3;              // window index 0..4095
    int h = blk & 7;
    int tid = threadIdx.x;
    int wid = tid >> 5, lane = tid & 31;

    for (int idx = tid; idx < NTOK * HD; idx += 256) {
        int n = idx >> 5, d = idx & 31;
        size_t base = ((size_t)b * NTOK + n) * TDIM + h * HD + d;
        sq[n][d] = g_qkv[base];
        sk[n][d] = g_qkv[base + 256];
        sv[n][d] = g_qkv[base + 512];
    }
    if (tid < 96) sk[49 + (tid >> 5)][tid & 31] = 0.f;
    if (tid < 3 * 52) sattn[49 + tid / 52][tid % 52] = 0.f;
    __syncthreads();

    float sc = expf(fminf(logit_scale[h], 4.60517019f));

    for (int r = wid; r < NTOK; r += 8) {
        float qv = sq[r][lane];
        float s = qv * qv;
#pragma unroll
        for (int o = 16; o; o >>= 1) s += __shfl_xor_sync(0xffffffffu, s, o);
        sq[r][lane] = qv * rsqrtf(s + 1e-6f) * sc;
        float kv = sk[r][lane];
        float s2 = kv * kv;
#pragma unroll
        for (int o = 16; o; o >>= 1) s2 += __shfl_xor_sync(0xffffffffu, s2, o);
        sk[r][lane] = kv * rsqrtf(s2 + 1e-6f);
    }
    __syncthreads();

    int wmask = (b & 63) * (NTOK * NTOK);
    for (int s = tid; s < NTOK * 13; s += 256) {
        int i = s / 13;
        int j0 = (s % 13) * 4;
        float a0 = 0.f, a1 = 0.f, a2 = 0.f, a3 = 0.f;
#pragma unroll
        for (int d = 0; d < HD; ++d) {
            float qv = sq[i][d];
            a0 = fmaf(qv, sk[j0 + 0][d], a0);
            a1 = fmaf(qv, sk[j0 + 1][d], a1);
            a2 = fmaf(qv, sk[j0 + 2][d], a2);
            a3 = fmaf(qv, sk[j0 + 3][d], a3);
        }
        float av[4] = {a0, a1, a2, a3};
#pragma unroll
        for (int u = 0; u < 4; ++u) {
            int j = j0 + u;
            if (j < NTOK) {
                float t = g_table[rpi[i * NTOK + j] * NH + h];
                float rpb = 16.f / (1.f + expf(-t));
                sattn[i][j] = av[u] + rpb + mask[wmask + i * NTOK + j];
            }
        }
    }
    __syncthreads();

    for (int r = wid; r < NTOK; r += 8) {
        float v0 = sattn[r][lane];
        float v1 = (lane + 32 < NTOK) ? sattn[r][lane + 32] : -1e30f;
        float mx = fmaxf(v0, v1);
#pragma unroll
        for (int o = 16; o; o >>= 1) mx = fmaxf(mx, __shfl_xor_sync(0xffffffffu, mx, o));
        float e0 = expf(v0 - mx);
        float e1 = (lane + 32 < NTOK) ? expf(v1 - mx) : 0.f;
        float sm = e0 + e1;
#pragma unroll
        for (int o = 16; o; o >>= 1) sm += __shfl_xor_sync(0xffffffffu, sm, o);
        float inv = 1.f / sm;
        sattn[r][lane] = e0 * inv;
        if (lane + 32 < NTOK) sattn[r][lane + 32] = e1 * inv;
    }
    __syncthreads();

    for (int s = tid; s < 13 * 32; s += 256) {
        int istrip = s >> 5;
        int d = s & 31;
        int i0 = istrip * 4;
        float o0 = 0.f, o1 = 0.f, o2 = 0.f, o3 = 0.f;
        for (int j = 0; j < NTOK; ++j) {
            float vv = sv[j][d];
            o0 = fmaf(sattn[i0 + 0][j], vv, o0);
            o1 = fmaf(sattn[i0 + 1][j], vv, o1);
            o2 = fmaf(sattn[i0 + 2][j], vv, o2);
            o3 = fmaf(sattn[i0 + 3][j], vv, o3);
        }
        float ov[4] = {o0, o1, o2, o3};
#pragma unroll
        for (int u = 0; u < 4; ++u) {
            int i = i0 + u;
            if (i < NTOK)
                g_attnout[((size_t)b * NTOK + i) * DIMC + h * HD + d] = ov[u];
        }
    }
}

// ---------------- launch ----------------
extern "C" void kernel_launch(void* const* d_in, const int* in_sizes, int n_in,
                              void* d_out, int out_size) {
    const float* x           = (const float*)d_in[0];
    const float* qkv_w       = (const float*)d_in[1];
    const float* q_bias      = (const float*)d_in[2];
    const float* v_bias      = (const float*)d_in[3];
    const float* logit_scale = (const float*)d_in[4];
    const float* cpb_w1      = (const float*)d_in[5];
    const float* cpb_b1      = (const float*)d_in[6];
    const float* cpb_w2      = (const float*)d_in[7];
    const float* coords      = (const float*)d_in[8];
    const int*   rpi         = (const int*)  d_in[9];
    const float* mask        = (const float*)d_in[10];
    const float* proj_w      = (const float*)d_in[11];
    const float* proj_b      = (const float*)d_in[12];
    float* out = (float*)d_out;

    float *qkv_ptr = nullptr, *ao_ptr = nullptr, *b768_ptr = nullptr;
    cudaGetSymbolAddress((void**)&qkv_ptr, g_qkv);
    cudaGetSymbolAddress((void**)&ao_ptr, g_attnout);
    cudaGetSymbolAddress((void**)&b768_ptr, g_bias768);

    fill_bias_kernel<<<1, 768>>>(q_bias, v_bias);
    cpb_table_kernel<<<169, 64>>>(coords, cpb_w1, cpb_b1, cpb_w2);

    // qkv = x @ qkv_w^T + [q_bias, 0, v_bias]   (TF32 tensor cores)
    gemm_tf32<<<dim3(TDIM / 128, MROWS / 128), 256>>>(
        x, qkv_w, b768_ptr, qkv_ptr, MROWS, TDIM, DIMC);

    // per-(window, head) cosine attention
    attn_kernel<<<BWIN * NH, 256>>>(logit_scale, rpi, mask);

    // out = attn_out @ proj_w^T + proj_b   (TF32 tensor cores)
    gemm_tf32<<<dim3(DIMC / 128, MROWS / 128), 256>>>(
        ao_ptr, proj_w, proj_b, out, MROWS, DIMC, DIMC);
}